// round 14
// baseline (speedup 1.0000x reference)
#include <cuda_runtime.h>
#include <cuda_fp16.h>
#include <cstdint>

// Problem constants
#define T_TOK  2048
#define N_NEU  11008
#define D_OUT  4096
#define K_TOK  2201      // int(11008 * 0.2)
#define N_CORE 4403      // int(11008 * 0.4)

// -------- device scratch (static, no runtime allocation) --------
__device__ int g_counts[N_NEU];
__device__ int g_hist[2049];
__device__ int g_off[2049];
__device__ int g_cursor[2049];
__device__ int g_scratch[N_NEU];

// fp16 W operand (X is consumed in f32 directly by the GEMM)
__device__ __half g_Wf[(size_t)D_OUT * N_NEU];

// ---------------- helpers ----------------
__device__ __forceinline__ uint32_t smem_u32(const void* p) {
    uint32_t a;
    asm("{ .reg .u64 t; cvta.to.shared.u64 t, %1; cvt.u32.u64 %0, t; }" : "=r"(a) : "l"(p));
    return a;
}
__device__ __forceinline__ void cp_async16(uint32_t saddr, const void* gaddr) {
    asm volatile("cp.async.cg.shared.global [%0], [%1], 16;" :: "r"(saddr), "l"(gaddr));
}
__device__ __forceinline__ void cp_commit() { asm volatile("cp.async.commit_group;"); }
__device__ __forceinline__ void cp_wait1()  { asm volatile("cp.async.wait_group 1;"); }

__device__ __forceinline__ void ldsm_x4(uint32_t& r0, uint32_t& r1, uint32_t& r2, uint32_t& r3,
                                        uint32_t addr) {
    asm volatile("ldmatrix.sync.aligned.m8n8.x4.shared.b16 {%0,%1,%2,%3}, [%4];"
                 : "=r"(r0), "=r"(r1), "=r"(r2), "=r"(r3) : "r"(addr));
}

#define MMA_F16(d, a, b)                                                      \
    asm volatile(                                                             \
        "mma.sync.aligned.m16n8k16.row.col.f32.f16.f16.f32 "                  \
        "{%0,%1,%2,%3}, {%4,%5,%6,%7}, {%8,%9}, {%0,%1,%2,%3};"               \
        : "+f"(d[0]), "+f"(d[1]), "+f"(d[2]), "+f"(d[3])                      \
        : "r"(a[0]), "r"(a[1]), "r"(a[2]), "r"(a[3]), "r"(b[0]), "r"(b[1]))

// order-preserving float -> uint map (ascending)
__device__ __forceinline__ unsigned int fkey(float f) {
    unsigned int u = __float_as_uint(f);
    return (u & 0x80000000u) ? ~u : (u | 0x80000000u);
}

// pack two f32 -> half2 bits (rn rounding, identical to __float2half_rn per lane)
__device__ __forceinline__ uint32_t f2_to_h2(float2 v) {
    __half2 h = __floats2half2_rn(v.x, v.y);
    return *reinterpret_cast<uint32_t*>(&h);
}

// -------- reset scratch each launch --------
__global__ void zero_kernel() {
    int i = blockIdx.x * blockDim.x + threadIdx.x;
    if (i < N_NEU) g_counts[i] = 0;
    if (i < 2049) { g_hist[i] = 0; g_cursor[i] = 0; }
}

// -------- W: f32 -> fp16 convert --------
__global__ void convert_kernel(const float* __restrict__ src,
                               __half* __restrict__ dst, int n4) {
    int i = blockIdx.x * blockDim.x + threadIdx.x;
    if (i >= n4) return;
    float4 v = ((const float4*)src)[i];
    ((__half2*)dst)[2 * i]     = __halves2half2(__float2half_rn(v.x), __float2half_rn(v.y));
    ((__half2*)dst)[2 * i + 1] = __halves2half2(__float2half_rn(v.z), __float2half_rn(v.w));
}

// -------- per-token exact top-K + vote count (512 thr, no Xf write) --------
#define TOPK_THREADS 512
#define TOPK_SMEM (N_NEU * 4 + 2048 * 4 + TOPK_THREADS * 4)
__global__ void topk_count_kernel(const float* __restrict__ X) {
    extern __shared__ char dsm[];
    float* row = (float*)dsm;
    unsigned int* h = (unsigned int*)(dsm + N_NEU * 4);
    int* s_part = (int*)(dsm + N_NEU * 4 + 2048 * 4);

    __shared__ unsigned int s_prefix;
    __shared__ int s_k;
    __shared__ int s_eq_n;
    __shared__ int s_eq_idx[64];

    const int t = blockIdx.x;
    const int tid = threadIdx.x;
    const float* grow = X + (size_t)t * N_NEU;

    if (tid == 0) { s_prefix = 0u; s_k = K_TOK; s_eq_n = 0; }

    for (int j = tid; j < N_NEU / 4; j += TOPK_THREADS)
        ((float4*)row)[j] = ((const float4*)grow)[j];
    __syncthreads();

    #pragma unroll
    for (int p = 0; p < 3; p++) {
        const int shift = (p == 0) ? 21 : (p == 1) ? 10 : 0;
        const int nbins = (p == 2) ? 1024 : 2048;
        const unsigned int himask =
            (p == 0) ? 0u : ((p == 1) ? (0xFFFFFFFFu << 21) : (0xFFFFFFFFu << 10));

        for (int i = tid; i < nbins; i += TOPK_THREADS) h[i] = 0u;
        __syncthreads();

        const unsigned int pre = s_prefix;
        for (int i = tid; i < N_NEU; i += TOPK_THREADS) {
            unsigned int u = fkey(row[i]);
            const bool act = ((u & himask) == pre);
            unsigned int bin = act ? ((u >> shift) & (unsigned)(nbins - 1)) : 0xFFFFFFFFu;
            unsigned int mm = __match_any_sync(__activemask(), bin);
            if (act) {
                int leader = __ffs(mm) - 1;
                if ((tid & 31) == leader) atomicAdd(&h[bin], (unsigned)__popc(mm));
            }
        }
        __syncthreads();

        const int nb_per = nbins / TOPK_THREADS;   // 4 or 2
        int lsum = 0;
        #pragma unroll 4
        for (int j = 0; j < nb_per; j++) lsum += (int)h[tid * nb_per + j];
        s_part[tid] = lsum;
        __syncthreads();
        #pragma unroll
        for (int off = 1; off < TOPK_THREADS; off <<= 1) {
            int v = s_part[tid];
            int add = (tid + off < TOPK_THREADS) ? s_part[tid + off] : 0;
            __syncthreads();
            s_part[tid] = v + add;
            __syncthreads();
        }
        const int k = s_k;
        const int above = (tid < TOPK_THREADS - 1) ? s_part[tid + 1] : 0;
        if (s_part[tid] >= k && above < k) {
            int cum = above;
            int d = tid * nb_per + nb_per - 1;
            for (; d > tid * nb_per; d--) {
                if (cum + (int)h[d] >= k) break;
                cum += (int)h[d];
            }
            s_k = k - cum;
            s_prefix = pre | ((unsigned int)d << shift);
        }
        __syncthreads();
    }

    const unsigned int thr = s_prefix;
    const int m = s_k;

    for (int i = tid; i < N_NEU; i += TOPK_THREADS) {
        unsigned int u = fkey(row[i]);
        if (u > thr) {
            atomicAdd(&g_counts[i], 1);
        } else if (u == thr) {
            int p = atomicAdd(&s_eq_n, 1);
            if (p < 64) s_eq_idx[p] = i;
        }
    }
    __syncthreads();

    if (tid == 0) {
        int n = s_eq_n; if (n > 64) n = 64;
        for (int a = 1; a < n; a++) {
            int v = s_eq_idx[a]; int b = a - 1;
            while (b >= 0 && s_eq_idx[b] > v) { s_eq_idx[b + 1] = s_eq_idx[b]; b--; }
            s_eq_idx[b + 1] = v;
        }
        int take = m; if (take > n) take = n;
        for (int j = 0; j < take; j++) atomicAdd(&g_counts[s_eq_idx[j]], 1);
    }
}

__global__ void hist_kernel() {
    int n = blockIdx.x * blockDim.x + threadIdx.x;
    if (n < N_NEU) atomicAdd(&g_hist[g_counts[n]], 1);
}

__global__ void scan_kernel() {
    __shared__ int sh[2049];
    for (int i = threadIdx.x; i < 2049; i += blockDim.x) sh[i] = g_hist[i];
    __syncthreads();
    if (threadIdx.x == 0) {
        int cum = 0;
        for (int c = 2048; c >= 0; c--) { g_off[c] = cum; cum += sh[c]; }
    }
}

__global__ void fill_kernel() {
    int n = blockIdx.x * blockDim.x + threadIdx.x;
    if (n < N_NEU) {
        int c = g_counts[n];
        int pos = g_off[c] + atomicAdd(&g_cursor[c], 1);
        g_scratch[pos] = n;
    }
}

__global__ void sort_kernel() {
    const int c = blockIdx.x;
    const int beg = g_off[c];
    const int cnt = g_hist[c];
    if (cnt <= 1) return;
    if (beg >= N_CORE) return;

    __shared__ int buf[2048];
    if (cnt <= 2048) {
        for (int i = threadIdx.x; i < cnt; i += blockDim.x) buf[i] = g_scratch[beg + i];
        __syncthreads();
        for (int ph = 0; ph < cnt; ph++) {
            int st = ph & 1;
            for (int i = threadIdx.x; st + 2 * i + 1 < cnt; i += blockDim.x) {
                int a = st + 2 * i;
                int u = buf[a], v = buf[a + 1];
                if (u > v) { buf[a] = v; buf[a + 1] = u; }
            }
            __syncthreads();
        }
        for (int i = threadIdx.x; i < cnt; i += blockDim.x) g_scratch[beg + i] = buf[i];
    } else {
        if (threadIdx.x == 0) {
            for (int a = beg + 1; a < beg + cnt; a++) {
                int v = g_scratch[a]; int b = a - 1;
                while (b >= beg && g_scratch[b] > v) { g_scratch[b + 1] = g_scratch[b]; b--; }
                g_scratch[b + 1] = v;
            }
        }
    }
}

__global__ void gather_kernel(const float* __restrict__ W, float* __restrict__ out2) {
    __shared__ float rowbuf[N_NEU];
    const int d = blockIdx.x;
    const float* wr = W + (size_t)d * N_NEU;
    for (int i = threadIdx.x; i < N_NEU / 4; i += blockDim.x)
        ((float4*)rowbuf)[i] = ((const float4*)wr)[i];
    __syncthreads();
    float* o = out2 + (size_t)d * N_CORE;
    for (int j = threadIdx.x; j < N_CORE; j += blockDim.x)
        o[j] = rowbuf[g_scratch[j]];
}

// ========= fp16 GEMM with f32 A: D = cvt(X) * Wf^T, 128x256 tile, 512 thr =========
// A staged in smem as f32; fragments converted in-register (same rn rounding as the
// old pre-converted path -> bit-identical result). B fp16 via ldmatrix as before.

#define GBM 128
#define GBN 256
#define GBK 32
#define ROWB_A 144                    // f32 A row: 128B data + 16B pad
#define ROWB_B 80                     // fp16 B row: 64B data + 16B pad
#define ARR_A (128 * ROWB_A)          // 18432 B
#define ARR_B (256 * ROWB_B)          // 20480 B
#define STG   (ARR_A + ARR_B)         // 38912 B per stage
#define NSTG 3
#define GEMM_SMEM (NSTG * STG)        // 116736 B
#define OFF_A  0
#define OFF_B  ARR_A
#define NIT (N_NEU / GBK)             // 344

__global__ __launch_bounds__(512, 1)
void gemm_mma_kernel(const float* __restrict__ X, float* __restrict__ C) {
    extern __shared__ char smem[];
    const uint32_t sb0 = smem_u32(smem);

    const int tid  = threadIdx.x;
    const int lane = tid & 31;
    const int wid  = tid >> 5;
    const int wm   = (wid & 1) * 64;
    const int wn   = (wid >> 1) * 32;

    const int bt = blockIdx.x * GBM;
    const int bd = blockIdx.y * GBN;

    const __half* Wf = g_Wf;

    // A: 1024 x 16B chunks (128 rows x 8), 2 per thread. chunk -> 4 f32.
    const int ra0 = tid >> 3,        ca0 = tid & 7;
    const int ra1 = 64 + (tid >> 3), ca1 = tid & 7;
    // B: 1024 x 16B chunks (256 rows x 4), 2 per thread. chunk -> 8 fp16.
    const int rb0 = tid >> 2,         cb0 = tid & 3;
    const int rb1 = (512 + tid) >> 2, cb1 = tid & 3;

    auto load_stage = [&](int it, int s) {
        const uint32_t sb = sb0 + s * STG;
        const int k0 = it * GBK;
        const size_t ga0 = (size_t)(bt + ra0) * N_NEU + k0 + ca0 * 4;
        const size_t ga1 = (size_t)(bt + ra1) * N_NEU + k0 + ca1 * 4;
        const size_t gw0 = (size_t)(bd + rb0) * N_NEU + k0 + cb0 * 8;
        const size_t gw1 = (size_t)(bd + rb1) * N_NEU + k0 + cb1 * 8;
        cp_async16(sb + OFF_A + (uint32_t)(ra0 * ROWB_A + ca0 * 16), X + ga0);
        cp_async16(sb + OFF_A + (uint32_t)(ra1 * ROWB_A + ca1 * 16), X + ga1);
        cp_async16(sb + OFF_B + (uint32_t)(rb0 * ROWB_B + cb0 * 16), Wf + gw0);
        cp_async16(sb + OFF_B + (uint32_t)(rb1 * ROWB_B + cb1 * 16), Wf + gw1);
    };

    float acc[4][4][4];
    #pragma unroll
    for (int i = 0; i < 4; i++)
        #pragma unroll
        for (int j = 0; j < 4; j++)
            #pragma unroll
            for (int r = 0; r < 4; r++) acc[i][j][r] = 0.0f;

    const int g   = lane >> 2;          // row-in-8 group
    const int tig = lane & 3;
    const int mi = lane >> 3, ri = lane & 7;
    // A fragment byte offsets (f32): row (wm + mt*16 + g [+8]), col (ks*16 + tig*2 [+8])
    const uint32_t a_base = (uint32_t)((wm + g) * ROWB_A + tig * 8);
    // B via ldmatrix (fp16), unchanged
    const uint32_t b_row_off = (uint32_t)((wn + (mi >> 1) * 8 + ri) * ROWB_B + (mi & 1) * 16);

    load_stage(0, 0); cp_commit();
    load_stage(1, 1); cp_commit();

    for (int it = 0; it < NIT; it++) {
        cp_wait1();
        __syncthreads();

        if (it + 2 < NIT) load_stage(it + 2, (it + 2) % NSTG);
        cp_commit();

        const int sidx = it % NSTG;
        const char* smA = smem + sidx * STG + OFF_A;
        const uint32_t aB = sb0 + sidx * STG + OFF_B + b_row_off;

        #pragma unroll
        for (int ks = 0; ks < 2; ks++) {
            const uint32_t kob = ks * 64;       // f32 bytes for 16 k-elements
            uint32_t bf[4][2];
            #pragma unroll
            for (int ntp = 0; ntp < 2; ntp++) {
                ldsm_x4(bf[2 * ntp][0], bf[2 * ntp][1], bf[2 * ntp + 1][0], bf[2 * ntp + 1][1],
                        aB + ks * 32 + (uint32_t)(ntp * 16 * ROWB_B));
            }
            #pragma unroll
            for (int mt = 0; mt < 4; mt++) {
                const char* ap = smA + a_base + kob + (uint32_t)(mt * 16 * ROWB_A);
                uint32_t ah[4];
                ah[0] = f2_to_h2(*(const float2*)(ap));
                ah[1] = f2_to_h2(*(const float2*)(ap + 8 * ROWB_A));
                ah[2] = f2_to_h2(*(const float2*)(ap + 32));
                ah[3] = f2_to_h2(*(const float2*)(ap + 8 * ROWB_A + 32));
                #pragma unroll
                for (int nt = 0; nt < 4; nt++) MMA_F16(acc[mt][nt], ah, bf[nt]);
            }
        }
    }

    // epilogue
    #pragma unroll
    for (int mt = 0; mt < 4; mt++) {
        #pragma unroll
        for (int nt = 0; nt < 4; nt++) {
            int t0 = bt + wm + mt * 16 + g;
            int d0 = bd + wn + nt * 8 + tig * 2;
            float2 v0 = make_float2(acc[mt][nt][0], acc[mt][nt][1]);
            float2 v1 = make_float2(acc[mt][nt][2], acc[mt][nt][3]);
            *(float2*)(C + (size_t)t0 * D_OUT + d0)       = v0;
            *(float2*)(C + (size_t)(t0 + 8) * D_OUT + d0) = v1;
        }
    }
}

extern "C" void kernel_launch(void* const* d_in, const int* in_sizes, int n_in,
                              void* d_out, int out_size) {
    const float* X = (const float*)d_in[0];
    const float* W = (const float*)d_in[1];
    float* out = (float*)d_out;
    (void)in_sizes; (void)n_in; (void)out_size;

    static cudaStream_t s1 = nullptr, s2 = nullptr;
    static cudaEvent_t e0 = nullptr, e1 = nullptr, e3 = nullptr;
    if (s1 == nullptr) {
        cudaStreamCreateWithFlags(&s1, cudaStreamNonBlocking);
        cudaStreamCreateWithFlags(&s2, cudaStreamNonBlocking);
        cudaEventCreateWithFlags(&e0, cudaEventDisableTiming);
        cudaEventCreateWithFlags(&e1, cudaEventDisableTiming);
        cudaEventCreateWithFlags(&e3, cudaEventDisableTiming);
        cudaFuncSetAttribute(gemm_mma_kernel, cudaFuncAttributeMaxDynamicSharedMemorySize, GEMM_SMEM);
        cudaFuncSetAttribute(topk_count_kernel, cudaFuncAttributeMaxDynamicSharedMemorySize, TOPK_SMEM);
    }

    __half* wf;
    cudaGetSymbolAddress((void**)&wf, g_Wf);

    // fork point
    cudaEventRecord(e0, 0);
    cudaStreamWaitEvent(s1, e0, 0);
    cudaStreamWaitEvent(s2, e0, 0);

    // s1: W fp16 convert (the only GEMM prerequisite)
    const int nw4 = (D_OUT * N_NEU) / 4;
    convert_kernel<<<(nw4 + 255) / 256, 256, 0, s1>>>(W, wf, nw4);
    cudaEventRecord(e1, s1);

    // s2: complete selection pipeline, fully concurrent with the GEMM
    zero_kernel<<<43, 256, 0, s2>>>();
    topk_count_kernel<<<T_TOK, TOPK_THREADS, TOPK_SMEM, s2>>>(X);
    hist_kernel<<<43, 256, 0, s2>>>();
    scan_kernel<<<1, 256, 0, s2>>>();
    fill_kernel<<<43, 256, 0, s2>>>();
    sort_kernel<<<2049, 128, 0, s2>>>();
    gather_kernel<<<D_OUT, 256, 0, s2>>>(W, out + (size_t)T_TOK * D_OUT);
    cudaEventRecord(e3, s2);

    // main: GEMM as soon as Wf is ready (X consumed in f32 directly)
    cudaStreamWaitEvent(0, e1, 0);
    dim3 ggrid(T_TOK / GBM, D_OUT / GBN);   // (16, 16)
    gemm_mma_kernel<<<ggrid, 512, GEMM_SMEM>>>(X, out);

    // join selection branch
    cudaStreamWaitEvent(0, e3, 0);
}

// round 15
// speedup vs baseline: 1.6656x; 1.6656x over previous
#include <cuda_runtime.h>
#include <cuda_fp16.h>
#include <cstdint>

// Problem constants
#define T_TOK  2048
#define N_NEU  11008
#define D_OUT  4096
#define K_TOK  2201      // int(11008 * 0.2)
#define N_CORE 4403      // int(11008 * 0.4)

// -------- device scratch (static, no runtime allocation) --------
__device__ int g_counts[N_NEU];
__device__ int g_hist[2049];
__device__ int g_off[2049];
__device__ int g_cursor[2049];
__device__ int g_scratch[N_NEU];

// fp16 operands
__device__ __half g_Xf[(size_t)T_TOK * N_NEU];
__device__ __half g_Wf[(size_t)D_OUT * N_NEU];

// ---------------- helpers ----------------
__device__ __forceinline__ uint32_t smem_u32(const void* p) {
    uint32_t a;
    asm("{ .reg .u64 t; cvta.to.shared.u64 t, %1; cvt.u32.u64 %0, t; }" : "=r"(a) : "l"(p));
    return a;
}
__device__ __forceinline__ void cp_async16(uint32_t saddr, const void* gaddr) {
    asm volatile("cp.async.cg.shared.global [%0], [%1], 16;" :: "r"(saddr), "l"(gaddr));
}
__device__ __forceinline__ void cp_commit() { asm volatile("cp.async.commit_group;"); }
__device__ __forceinline__ void cp_wait0()  { asm volatile("cp.async.wait_group 0;"); }

__device__ __forceinline__ void ldsm_x4(uint32_t& r0, uint32_t& r1, uint32_t& r2, uint32_t& r3,
                                        uint32_t addr) {
    asm volatile("ldmatrix.sync.aligned.m8n8.x4.shared.b16 {%0,%1,%2,%3}, [%4];"
                 : "=r"(r0), "=r"(r1), "=r"(r2), "=r"(r3) : "r"(addr));
}

#define MMA_F16(d, a, b)                                                      \
    asm volatile(                                                             \
        "mma.sync.aligned.m16n8k16.row.col.f32.f16.f16.f32 "                  \
        "{%0,%1,%2,%3}, {%4,%5,%6,%7}, {%8,%9}, {%0,%1,%2,%3};"               \
        : "+f"(d[0]), "+f"(d[1]), "+f"(d[2]), "+f"(d[3])                      \
        : "r"(a[0]), "r"(a[1]), "r"(a[2]), "r"(a[3]), "r"(b[0]), "r"(b[1]))

// order-preserving float -> uint map (ascending)
__device__ __forceinline__ unsigned int fkey(float f) {
    unsigned int u = __float_as_uint(f);
    return (u & 0x80000000u) ? ~u : (u | 0x80000000u);
}

// -------- reset scratch each launch --------
__global__ void zero_kernel() {
    int i = blockIdx.x * blockDim.x + threadIdx.x;
    if (i < N_NEU) g_counts[i] = 0;
    if (i < 2049) { g_hist[i] = 0; g_cursor[i] = 0; }
}

// -------- W: f32 -> fp16 convert --------
__global__ void convert_kernel(const float* __restrict__ src,
                               __half* __restrict__ dst, int n4) {
    int i = blockIdx.x * blockDim.x + threadIdx.x;
    if (i >= n4) return;
    float4 v = ((const float4*)src)[i];
    ((__half2*)dst)[2 * i]     = __halves2half2(__float2half_rn(v.x), __float2half_rn(v.y));
    ((__half2*)dst)[2 * i + 1] = __halves2half2(__float2half_rn(v.z), __float2half_rn(v.w));
}

// -------- per-token exact top-K + vote count + fused X fp16 convert (512 thr) --------
#define TOPK_THREADS 512
#define TOPK_SMEM (N_NEU * 4 + 2048 * 4 + TOPK_THREADS * 4)
__global__ void topk_count_kernel(const float* __restrict__ X,
                                  __half* __restrict__ Xf) {
    extern __shared__ char dsm[];
    float* row = (float*)dsm;
    unsigned int* h = (unsigned int*)(dsm + N_NEU * 4);
    int* s_part = (int*)(dsm + N_NEU * 4 + 2048 * 4);

    __shared__ unsigned int s_prefix;
    __shared__ int s_k;
    __shared__ int s_eq_n;
    __shared__ int s_eq_idx[64];

    const int t = blockIdx.x;
    const int tid = threadIdx.x;
    const float* grow = X + (size_t)t * N_NEU;
    __half* gxf = Xf + (size_t)t * N_NEU;

    if (tid == 0) { s_prefix = 0u; s_k = K_TOK; s_eq_n = 0; }

    for (int j = tid; j < N_NEU / 4; j += TOPK_THREADS) {
        float4 v = ((const float4*)grow)[j];
        ((float4*)row)[j] = v;
        ((__half2*)gxf)[2 * j]     = __halves2half2(__float2half_rn(v.x), __float2half_rn(v.y));
        ((__half2*)gxf)[2 * j + 1] = __halves2half2(__float2half_rn(v.z), __float2half_rn(v.w));
    }
    __syncthreads();

    #pragma unroll
    for (int p = 0; p < 3; p++) {
        const int shift = (p == 0) ? 21 : (p == 1) ? 10 : 0;
        const int nbins = (p == 2) ? 1024 : 2048;
        const unsigned int himask =
            (p == 0) ? 0u : ((p == 1) ? (0xFFFFFFFFu << 21) : (0xFFFFFFFFu << 10));

        for (int i = tid; i < nbins; i += TOPK_THREADS) h[i] = 0u;
        __syncthreads();

        const unsigned int pre = s_prefix;
        for (int i = tid; i < N_NEU; i += TOPK_THREADS) {
            unsigned int u = fkey(row[i]);
            const bool act = ((u & himask) == pre);
            unsigned int bin = act ? ((u >> shift) & (unsigned)(nbins - 1)) : 0xFFFFFFFFu;
            unsigned int mm = __match_any_sync(__activemask(), bin);
            if (act) {
                int leader = __ffs(mm) - 1;
                if ((tid & 31) == leader) atomicAdd(&h[bin], (unsigned)__popc(mm));
            }
        }
        __syncthreads();

        const int nb_per = nbins / TOPK_THREADS;   // 4 or 2
        int lsum = 0;
        #pragma unroll 4
        for (int j = 0; j < nb_per; j++) lsum += (int)h[tid * nb_per + j];
        s_part[tid] = lsum;
        __syncthreads();
        #pragma unroll
        for (int off = 1; off < TOPK_THREADS; off <<= 1) {
            int v = s_part[tid];
            int add = (tid + off < TOPK_THREADS) ? s_part[tid + off] : 0;
            __syncthreads();
            s_part[tid] = v + add;
            __syncthreads();
        }
        const int k = s_k;
        const int above = (tid < TOPK_THREADS - 1) ? s_part[tid + 1] : 0;
        if (s_part[tid] >= k && above < k) {       // exactly one owner thread
            int cum = above;
            int d = tid * nb_per + nb_per - 1;
            for (; d > tid * nb_per; d--) {
                if (cum + (int)h[d] >= k) break;
                cum += (int)h[d];
            }
            s_k = k - cum;
            s_prefix = pre | ((unsigned int)d << shift);
        }
        __syncthreads();
    }

    const unsigned int thr = s_prefix;
    const int m = s_k;

    for (int i = tid; i < N_NEU; i += TOPK_THREADS) {
        unsigned int u = fkey(row[i]);
        if (u > thr) {
            atomicAdd(&g_counts[i], 1);
        } else if (u == thr) {
            int p = atomicAdd(&s_eq_n, 1);
            if (p < 64) s_eq_idx[p] = i;
        }
    }
    __syncthreads();

    if (tid == 0) {
        int n = s_eq_n; if (n > 64) n = 64;
        for (int a = 1; a < n; a++) {
            int v = s_eq_idx[a]; int b = a - 1;
            while (b >= 0 && s_eq_idx[b] > v) { s_eq_idx[b + 1] = s_eq_idx[b]; b--; }
            s_eq_idx[b + 1] = v;
        }
        int take = m; if (take > n) take = n;
        for (int j = 0; j < take; j++) atomicAdd(&g_counts[s_eq_idx[j]], 1);
    }
}

__global__ void hist_kernel() {
    int n = blockIdx.x * blockDim.x + threadIdx.x;
    if (n < N_NEU) atomicAdd(&g_hist[g_counts[n]], 1);
}

__global__ void scan_kernel() {
    __shared__ int sh[2049];
    for (int i = threadIdx.x; i < 2049; i += blockDim.x) sh[i] = g_hist[i];
    __syncthreads();
    if (threadIdx.x == 0) {
        int cum = 0;
        for (int c = 2048; c >= 0; c--) { g_off[c] = cum; cum += sh[c]; }
    }
}

__global__ void fill_kernel() {
    int n = blockIdx.x * blockDim.x + threadIdx.x;
    if (n < N_NEU) {
        int c = g_counts[n];
        int pos = g_off[c] + atomicAdd(&g_cursor[c], 1);
        g_scratch[pos] = n;
    }
}

__global__ void sort_kernel() {
    const int c = blockIdx.x;
    const int beg = g_off[c];
    const int cnt = g_hist[c];
    if (cnt <= 1) return;
    if (beg >= N_CORE) return;

    __shared__ int buf[2048];
    if (cnt <= 2048) {
        for (int i = threadIdx.x; i < cnt; i += blockDim.x) buf[i] = g_scratch[beg + i];
        __syncthreads();
        for (int ph = 0; ph < cnt; ph++) {
            int st = ph & 1;
            for (int i = threadIdx.x; st + 2 * i + 1 < cnt; i += blockDim.x) {
                int a = st + 2 * i;
                int u = buf[a], v = buf[a + 1];
                if (u > v) { buf[a] = v; buf[a + 1] = u; }
            }
            __syncthreads();
        }
        for (int i = threadIdx.x; i < cnt; i += blockDim.x) g_scratch[beg + i] = buf[i];
    } else {
        if (threadIdx.x == 0) {
            for (int a = beg + 1; a < beg + cnt; a++) {
                int v = g_scratch[a]; int b = a - 1;
                while (b >= beg && g_scratch[b] > v) { g_scratch[b + 1] = g_scratch[b]; b--; }
                g_scratch[b + 1] = v;
            }
        }
    }
}

__global__ void gather_kernel(const float* __restrict__ W, float* __restrict__ out2) {
    __shared__ float rowbuf[N_NEU];
    const int d = blockIdx.x;
    const float* wr = W + (size_t)d * N_NEU;
    for (int i = threadIdx.x; i < N_NEU / 4; i += blockDim.x)
        ((float4*)rowbuf)[i] = ((const float4*)wr)[i];
    __syncthreads();
    float* o = out2 + (size_t)d * N_CORE;
    for (int j = threadIdx.x; j < N_CORE; j += blockDim.x)
        o[j] = rowbuf[g_scratch[j]];
}

// ========= pure fp16 GEMM: D = Xf * Wf^T, 128x256 tile, 512 thr, BK=64, 2-stage =========
// 16 warps (2M x 8N), warp tile 64x32. One wait + one sync per 64-k tile (NIT=172).

#define GBM 128
#define GBN 256
#define GBK 64
#define ROWB 144                      // 128B data + 16B pad (R5-verified geometry)
#define ARR_A (128 * ROWB)            // 18432 B
#define ARR_B (256 * ROWB)            // 36864 B
#define STG   (ARR_A + ARR_B)         // 55296 B per stage
#define NSTG 2
#define GEMM_SMEM (NSTG * STG)        // 110592 B
#define OFF_A  0
#define OFF_B  ARR_A
#define NIT (N_NEU / GBK)             // 172

__global__ __launch_bounds__(512, 1)
void gemm_mma_kernel(float* __restrict__ C) {
    extern __shared__ char smem[];
    const uint32_t sb0 = smem_u32(smem);

    const int tid  = threadIdx.x;
    const int lane = tid & 31;
    const int wid  = tid >> 5;
    const int wm   = (wid & 1) * 64;
    const int wn   = (wid >> 1) * 32;

    const int bt = blockIdx.x * GBM;
    const int bd = blockIdx.y * GBN;

    const __half* Xf = g_Xf;
    const __half* Wf = g_Wf;

    auto load_stage = [&](int it, int s) {
        const uint32_t sb = sb0 + s * STG;
        const int k0 = it * GBK;
        #pragma unroll
        for (int i = 0; i < 2; i++) {
            const int q = i * 512 + tid;
            const int r = q >> 3, c = q & 7;
            cp_async16(sb + OFF_A + (uint32_t)(r * ROWB + c * 16),
                       Xf + (size_t)(bt + r) * N_NEU + k0 + c * 8);
        }
        #pragma unroll
        for (int i = 0; i < 4; i++) {
            const int q = i * 512 + tid;
            const int r = q >> 3, c = q & 7;
            cp_async16(sb + OFF_B + (uint32_t)(r * ROWB + c * 16),
                       Wf + (size_t)(bd + r) * N_NEU + k0 + c * 8);
        }
        cp_commit();
    };

    float acc[4][4][4];
    #pragma unroll
    for (int i = 0; i < 4; i++)
        #pragma unroll
        for (int j = 0; j < 4; j++)
            #pragma unroll
            for (int r = 0; r < 4; r++) acc[i][j][r] = 0.0f;

    const int mi = lane >> 3, ri = lane & 7;
    const uint32_t a_row_off = (uint32_t)((wm + (mi & 1) * 8 + ri) * ROWB + (mi >> 1) * 16);
    const uint32_t b_row_off = (uint32_t)((wn + (mi >> 1) * 8 + ri) * ROWB + (mi & 1) * 16);

    load_stage(0, 0);

    for (int it = 0; it < NIT; it++) {
        cp_wait0();
        __syncthreads();

        if (it + 1 < NIT) load_stage(it + 1, (it + 1) & 1);

        const uint32_t sb = sb0 + (it & 1) * STG;
        const uint32_t aA = sb + OFF_A + a_row_off;
        const uint32_t aB = sb + OFF_B + b_row_off;

        #pragma unroll
        for (int ks = 0; ks < 4; ks++) {
            const uint32_t ko = ks * 32;
            uint32_t bf[4][2];
            #pragma unroll
            for (int ntp = 0; ntp < 2; ntp++) {
                ldsm_x4(bf[2 * ntp][0], bf[2 * ntp][1], bf[2 * ntp + 1][0], bf[2 * ntp + 1][1],
                        aB + ko + (uint32_t)(ntp * 16 * ROWB));
            }
            #pragma unroll
            for (int mt = 0; mt < 4; mt++) {
                uint32_t ah[4];
                ldsm_x4(ah[0], ah[1], ah[2], ah[3], aA + ko + (uint32_t)(mt * 16 * ROWB));
                #pragma unroll
                for (int nt = 0; nt < 4; nt++) MMA_F16(acc[mt][nt], ah, bf[nt]);
            }
        }
    }

    // epilogue
    const int g   = lane >> 2;
    const int tig = lane & 3;
    #pragma unroll
    for (int mt = 0; mt < 4; mt++) {
        #pragma unroll
        for (int nt = 0; nt < 4; nt++) {
            int t0 = bt + wm + mt * 16 + g;
            int d0 = bd + wn + nt * 8 + tig * 2;
            float2 v0 = make_float2(acc[mt][nt][0], acc[mt][nt][1]);
            float2 v1 = make_float2(acc[mt][nt][2], acc[mt][nt][3]);
            *(float2*)(C + (size_t)t0 * D_OUT + d0)       = v0;
            *(float2*)(C + (size_t)(t0 + 8) * D_OUT + d0) = v1;
        }
    }
}

extern "C" void kernel_launch(void* const* d_in, const int* in_sizes, int n_in,
                              void* d_out, int out_size) {
    const float* X = (const float*)d_in[0];
    const float* W = (const float*)d_in[1];
    float* out = (float*)d_out;
    (void)in_sizes; (void)n_in; (void)out_size;

    static cudaStream_t s1 = nullptr, s2 = nullptr;
    static cudaEvent_t e0 = nullptr, e1 = nullptr, e2 = nullptr, e3 = nullptr;
    if (s1 == nullptr) {
        cudaStreamCreateWithFlags(&s1, cudaStreamNonBlocking);
        cudaStreamCreateWithFlags(&s2, cudaStreamNonBlocking);
        cudaEventCreateWithFlags(&e0, cudaEventDisableTiming);
        cudaEventCreateWithFlags(&e1, cudaEventDisableTiming);
        cudaEventCreateWithFlags(&e2, cudaEventDisableTiming);
        cudaEventCreateWithFlags(&e3, cudaEventDisableTiming);
        cudaFuncSetAttribute(gemm_mma_kernel, cudaFuncAttributeMaxDynamicSharedMemorySize, GEMM_SMEM);
        cudaFuncSetAttribute(topk_count_kernel, cudaFuncAttributeMaxDynamicSharedMemorySize, TOPK_SMEM);
    }

    __half *xf, *wf;
    cudaGetSymbolAddress((void**)&xf, g_Xf);
    cudaGetSymbolAddress((void**)&wf, g_Wf);

    // fork: convert_W on s1 runs under topk
    cudaEventRecord(e0, 0);
    cudaStreamWaitEvent(s1, e0, 0);
    const int nw4 = (D_OUT * N_NEU) / 4;
    convert_kernel<<<(nw4 + 255) / 256, 256, 0, s1>>>(W, wf, nw4);
    cudaEventRecord(e1, s1);

    // main: zero + topk (produces Xf and g_counts)
    zero_kernel<<<43, 256>>>();
    topk_count_kernel<<<T_TOK, TOPK_THREADS, TOPK_SMEM>>>(X, xf);
    cudaEventRecord(e2, 0);

    // s2: selection tail + gather, concurrent with (and backfilling) the GEMM
    cudaStreamWaitEvent(s2, e2, 0);
    hist_kernel<<<43, 256, 0, s2>>>();
    scan_kernel<<<1, 256, 0, s2>>>();
    fill_kernel<<<43, 256, 0, s2>>>();
    sort_kernel<<<2049, 128, 0, s2>>>();
    gather_kernel<<<D_OUT, 256, 0, s2>>>(W, out + (size_t)T_TOK * D_OUT);
    cudaEventRecord(e3, s2);

    // main: GEMM (after W convert)
    cudaStreamWaitEvent(0, e1, 0);
    dim3 ggrid(T_TOK / GBM, D_OUT / GBN);   // (16, 16)
    gemm_mma_kernel<<<ggrid, 512, GEMM_SMEM>>>(out);

    // join selection branch
    cudaStreamWaitEvent(0, e3, 0);
}